// round 1
// baseline (speedup 1.0000x reference)
#include <cuda_runtime.h>

// Problem constants (fixed shapes per reference)
#define IN_C   32
#define OUT_C  64
#define HW     256
#define KK     9

// Tile config
#define TW 32
#define TH 8
#define XROWS (TH + 2)
#define XCOLS (TW + 2)
#define XTILE (IN_C * XROWS * XCOLS)   // 32*10*34 = 10880 floats
#define WSLAB 2052                      // 2048 + 4 pad (bank decorrelation of slab select)
#define SMEM_FLOATS (XTILE + 3 * WSLAB) // 17036 floats = 68144 bytes

// Pre-transposed weights: layout [p][i][c][o], contiguous per p for coalesced smem staging.
__device__ float g_wt[KK * 3 * IN_C * OUT_C];

__global__ void prep_weights(const float* __restrict__ w0,
                             const float* __restrict__ w1,
                             const float* __restrict__ w2) {
    int idx = blockIdx.x * blockDim.x + threadIdx.x;
    if (idx >= KK * 3 * IN_C * OUT_C) return;
    int p  = idx / (3 * IN_C * OUT_C);
    int r  = idx % (3 * IN_C * OUT_C);
    int i  = r / (IN_C * OUT_C);
    int r2 = r % (IN_C * OUT_C);
    int c  = r2 / OUT_C;
    int o  = r2 % OUT_C;
    const float* w = (i == 0) ? w0 : (i == 1) ? w1 : w2;
    // source layout: (OUT_C, IN_C, 3, 3) => w[o][c][p]
    g_wt[idx] = w[(o * IN_C + c) * KK + p];
}

__global__ void __launch_bounds__(TW * TH, 2)
conv25d_kernel(const float* __restrict__ x,
               const float* __restrict__ disp,
               const float* __restrict__ fxp,
               const float* __restrict__ blp,
               float* __restrict__ out) {
    extern __shared__ float sm[];
    float* xs = sm;                 // [c][row(10)][col(34)]
    float* ws = sm + XTILE;         // 3 slabs of WSLAB: [i][c][o(64)]

    const int tx  = threadIdx.x;
    const int ty  = threadIdx.y;
    const int tid = ty * TW + tx;
    const int n   = blockIdx.z;
    const int w0pix = blockIdx.x * TW;
    const int h0    = blockIdx.y * TH;

    const float* xb = x + (size_t)n * IN_C * HW * HW;
    const float* db = disp + (size_t)n * HW * HW;

    // ---- load x tile (zero-padded halo) ----
    for (int j = tid; j < XTILE; j += TW * TH) {
        int c   = j / (XROWS * XCOLS);
        int r   = j % (XROWS * XCOLS);
        int row = r / XCOLS;
        int col = r % XCOLS;
        int gy = h0 + row - 1;
        int gx = w0pix + col - 1;
        float v = 0.0f;
        if (gy >= 0 && gy < HW && gx >= 0 && gx < HW)
            v = xb[c * (HW * HW) + gy * HW + gx];
        xs[j] = v;
    }

    const int hh = h0 + ty;
    const int ww = w0pix + tx;

    // ---- mask precomputation (bit-exact fp32 to match reference) ----
    const float fxv = fxp[n];
    const float bf  = __fmul_rn(blp[n], fxv);   // baseline * fx

    const float dC = db[hh * HW + ww];
    const bool validC = (dC != 0.0f);
    const float depthC = __fdiv_rn(bf, fminf(fmaxf(validC ? dC : 0.0f, 0.01f), 256.0f));
    const float gr   = __fdiv_rn(__fmul_rn(16.0f, depthC), fxv);
    const float halfr = __fmul_rn(gr, 0.5f);

    float acc[OUT_C];
#pragma unroll
    for (int o = 0; o < OUT_C; o++) acc[o] = 0.0f;

    const int xoffbase = ty * XCOLS + tx; // +di*XCOLS + dj added per p

    for (int p = 0; p < KK; p++) {
        __syncthreads();   // previous p's weight use done
        // stage weights for this p: [i][c][o] -> slabs with pad
        for (int j = tid; j < 3 * IN_C * OUT_C; j += TW * TH) {
            int i = j >> 11;            // /2048
            int r = j & 2047;
            ws[i * WSLAB + r] = g_wt[p * (3 * IN_C * OUT_C) + j];
        }
        __syncthreads();

        const int di = p / 3, dj = p % 3;
        int gy = hh + di - 1, gx = ww + dj - 1;
        float dp = 0.0f;
        if (gy >= 0 && gy < HW && gx >= 0 && gx < HW) dp = db[gy * HW + gx];

        const bool valid = (dp != 0.0f) && validC;
        const float depth = __fdiv_rn(bf, fminf(fmaxf(valid ? dp : 0.0f, 0.01f), 256.0f));

        const float m0 = (fabsf(__fsub_rn(depth, __fadd_rn(depthC, gr))) <= halfr) ? 1.0f : 0.0f;
        const float ind = (fabsf(__fsub_rn(depth, depthC)) <= halfr) ? 1.0f : 0.0f;
        const float m1 = valid ? ind : 1.0f;
        const float m2 = (fabsf(__fsub_rn(depth, __fsub_rn(depthC, gr))) <= halfr) ? 1.0f : 0.0f;

        const float msum = m0 + m1 + m2;
        unsigned anyact = __ballot_sync(0xffffffffu, msum > 0.0f);
        if (anyact == 0) continue;                       // warp-uniform skip
        unsigned multi = __ballot_sync(0xffffffffu, msum > 1.5f);

        const int xoff = xoffbase + di * XCOLS + dj;
        const float* xcol = xs + xoff;

        if (multi == 0) {
            // masks exclusive: exactly one of w0/w1/w2 (or none) applies per thread
            const int sel = (m1 != 0.0f) ? 1 : ((m0 != 0.0f) ? 0 : 2);
            const float act = msum;                       // 0.0 or 1.0
            const float4* wv = (const float4*)(ws + sel * WSLAB);
#pragma unroll 2
            for (int c = 0; c < IN_C; c++) {
                const float t = xcol[c * (XROWS * XCOLS)] * act;
                const float4* wc = wv + c * (OUT_C / 4);
#pragma unroll
                for (int o4 = 0; o4 < OUT_C / 4; o4++) {
                    float4 wq = wc[o4];
                    acc[o4 * 4 + 0] = fmaf(t, wq.x, acc[o4 * 4 + 0]);
                    acc[o4 * 4 + 1] = fmaf(t, wq.y, acc[o4 * 4 + 1]);
                    acc[o4 * 4 + 2] = fmaf(t, wq.z, acc[o4 * 4 + 2]);
                    acc[o4 * 4 + 3] = fmaf(t, wq.w, acc[o4 * 4 + 3]);
                }
            }
        } else {
            // rare boundary-tie fallback: dense 3-weight accumulation
            const float4* wv0 = (const float4*)(ws);
            const float4* wv1 = (const float4*)(ws + WSLAB);
            const float4* wv2 = (const float4*)(ws + 2 * WSLAB);
#pragma unroll 1
            for (int c = 0; c < IN_C; c++) {
                const float xv = xcol[c * (XROWS * XCOLS)];
                const float t0 = xv * m0, t1 = xv * m1, t2 = xv * m2;
                const int cb = c * (OUT_C / 4);
#pragma unroll
                for (int o4 = 0; o4 < OUT_C / 4; o4++) {
                    float4 a = wv0[cb + o4];
                    float4 b = wv1[cb + o4];
                    float4 d = wv2[cb + o4];
                    acc[o4 * 4 + 0] = fmaf(t0, a.x, fmaf(t1, b.x, fmaf(t2, d.x, acc[o4 * 4 + 0])));
                    acc[o4 * 4 + 1] = fmaf(t0, a.y, fmaf(t1, b.y, fmaf(t2, d.y, acc[o4 * 4 + 1])));
                    acc[o4 * 4 + 2] = fmaf(t0, a.z, fmaf(t1, b.z, fmaf(t2, d.z, acc[o4 * 4 + 2])));
                    acc[o4 * 4 + 3] = fmaf(t0, a.w, fmaf(t1, b.w, fmaf(t2, d.w, acc[o4 * 4 + 3])));
                }
            }
        }
    }

    // ---- write output: out[n][o][h][w] ----
    size_t outbase = ((size_t)n * OUT_C) * (HW * HW) + (size_t)hh * HW + ww;
#pragma unroll
    for (int o = 0; o < OUT_C; o++)
        out[outbase + (size_t)o * (HW * HW)] = acc[o];
}

extern "C" void kernel_launch(void* const* d_in, const int* in_sizes, int n_in,
                              void* d_out, int out_size) {
    const float* x    = (const float*)d_in[0];
    const float* disp = (const float*)d_in[1];
    const float* fx   = (const float*)d_in[2];
    const float* bl   = (const float*)d_in[3];
    const float* w0   = (const float*)d_in[4];
    const float* w1   = (const float*)d_in[5];
    const float* w2   = (const float*)d_in[6];
    float* out = (float*)d_out;

    prep_weights<<<(KK * 3 * IN_C * OUT_C + 255) / 256, 256>>>(w0, w1, w2);

    cudaFuncSetAttribute(conv25d_kernel,
                         cudaFuncAttributeMaxDynamicSharedMemorySize,
                         SMEM_FLOATS * sizeof(float));

    dim3 grid(HW / TW, HW / TH, 2);
    dim3 block(TW, TH);
    conv25d_kernel<<<grid, block, SMEM_FLOATS * sizeof(float)>>>(x, disp, fx, bl, out);
}

// round 3
// speedup vs baseline: 2.9773x; 2.9773x over previous
#include <cuda_runtime.h>
#include <cstdint>

#define KK     9
#define IN_C   32
#define OUT_C  64
#define HWDIM  256
#define NTH    256

// smem (floats): xs [128][36], ws [3][32][72], msp [3][128]
#define XS_PITCH 36
#define WS_PITCH 72
#define OFF_WS   (128 * XS_PITCH)                 // 4608
#define OFF_MS   (OFF_WS + 3 * IN_C * WS_PITCH)   // 4608 + 6912 = 11520
#define SMEM_FLOATS (OFF_MS + 3 * 128)            // 11904 floats = 47616 B (< 48KB static)
#define OB_PITCH 132                              // epilogue buffer [64][132] reuses sm[0..8448)

// weights pre-transposed + pre-converted to tf32 bit patterns:
// g_wt2[((p*3+i)*IN_C + c)*OUT_C + o]
__device__ float g_wt2[KK * 3 * IN_C * OUT_C];

__global__ void prep_weights(const float* __restrict__ w0,
                             const float* __restrict__ w1,
                             const float* __restrict__ w2) {
    int idx = blockIdx.x * blockDim.x + threadIdx.x;
    if (idx >= KK * 3 * IN_C * OUT_C) return;
    int o  = idx & 63;
    int c  = (idx >> 6) & 31;
    int pi = idx >> 11;           // p*3 + i
    int i  = pi % 3;
    int p  = pi / 3;
    const float* w = (i == 0) ? w0 : (i == 1) ? w1 : w2;
    float v = w[(o * IN_C + c) * KK + p];
    uint32_t u;
    asm("cvt.rna.tf32.f32 %0, %1;" : "=r"(u) : "f"(v));
    g_wt2[idx] = __uint_as_float(u);
}

__device__ __forceinline__ void mma_tf32(float* d, const uint32_t* a, const uint32_t* b) {
    asm volatile(
        "mma.sync.aligned.m16n8k8.row.col.f32.tf32.tf32.f32 "
        "{%0,%1,%2,%3}, {%4,%5,%6,%7}, {%8,%9}, {%0,%1,%2,%3};"
        : "+f"(d[0]), "+f"(d[1]), "+f"(d[2]), "+f"(d[3])
        : "r"(a[0]), "r"(a[1]), "r"(a[2]), "r"(a[3]), "r"(b[0]), "r"(b[1]));
}

__global__ void __launch_bounds__(NTH)
conv25d_mma(const float* __restrict__ x,
            const float* __restrict__ disp,
            const float* __restrict__ fxp,
            const float* __restrict__ blp,
            float* __restrict__ out) {
    __shared__ float sm[SMEM_FLOATS];
    float* xs  = sm;
    float* ws  = sm + OFF_WS;
    float* msp = sm + OFF_MS;

    const int tid  = threadIdx.x;
    const int lane = tid & 31;
    const int wrp  = tid >> 5;
    const int jb   = (wrp & 3) << 5;   // pixel-group base (0,32,64,96)
    const int ob   = (wrp >> 2) << 5;  // out-channel half (0,32)

    const int b   = blockIdx.x;        // 1024 CTAs
    const int n   = b >> 9;
    const int rem = b & 511;
    const int h   = rem >> 1;
    const int wb  = (rem & 1) << 7;

    const float* xb = x + (size_t)n * IN_C * (HWDIM * HWDIM);
    const float* db = disp + (size_t)n * (HWDIM * HWDIM);

    // ---- per-pixel center quantities (thread tid handles pixel j=tid; exact fp32) ----
    float bf = 0.f, depthC = 0.f, grv = 0.f, halfv = 0.f;
    bool validC = false;
    if (tid < 128) {
        const float fxv = fxp[n];
        bf = __fmul_rn(blp[n], fxv);
        float dC = db[h * HWDIM + wb + tid];
        validC = (dC != 0.0f);
        depthC = __fdiv_rn(bf, fminf(fmaxf(validC ? dC : 0.0f, 0.01f), 256.0f));
        grv    = __fdiv_rn(__fmul_rn(16.0f, depthC), fxv);
        halfv  = __fmul_rn(grv, 0.5f);
    }

    float acc[2][4][4];
#pragma unroll
    for (int mt = 0; mt < 2; mt++)
#pragma unroll
        for (int n8 = 0; n8 < 4; n8++)
#pragma unroll
            for (int q = 0; q < 4; q++) acc[mt][n8][q] = 0.0f;

    const int r0 = jb + (lane >> 2);   // base A row for this lane
    const int cl = lane & 3;

    for (int p = 0; p < KK; p++) {
        __syncthreads();               // previous iteration's smem reads done

        const int di = p / 3, dj = p % 3;
        const int gy  = h + di - 1;
        const int gxs = wb + dj - 1;
        const bool rowok = (gy >= 0) && (gy < HWDIM);

        // masks for this p (pixel j = tid), bit-exact fp32
        if (tid < 128) {
            const int gx = gxs + tid;
            float dp = 0.0f;
            if (rowok && gx >= 0 && gx < HWDIM) dp = db[gy * HWDIM + gx];
            const bool valid = (dp != 0.0f) && validC;
            const float depth = __fdiv_rn(bf, fminf(fmaxf(valid ? dp : 0.0f, 0.01f), 256.0f));
            const float m0 = (fabsf(__fsub_rn(depth, __fadd_rn(depthC, grv))) <= halfv) ? 1.0f : 0.0f;
            const float ind = (fabsf(__fsub_rn(depth, depthC)) <= halfv) ? 1.0f : 0.0f;
            const float m1 = valid ? ind : 1.0f;
            const float m2 = (fabsf(__fsub_rn(depth, __fsub_rn(depthC, grv))) <= halfv) ? 1.0f : 0.0f;
            msp[tid] = m0; msp[128 + tid] = m1; msp[256 + tid] = m2;
        }

        // stage x row (tf32-converted): xs[j][c]
#pragma unroll
        for (int it = 0; it < 16; it++) {
            int e = tid + it * NTH;    // 0..4095
            int c = e >> 7;
            int j = e & 127;
            int gx = gxs + j;
            float v = 0.0f;
            if (rowok && gx >= 0 && gx < HWDIM)
                v = xb[c * (HWDIM * HWDIM) + gy * HWDIM + gx];
            uint32_t u;
            asm("cvt.rna.tf32.f32 %0, %1;" : "=r"(u) : "f"(v));
            xs[j * XS_PITCH + c] = __uint_as_float(u);
        }

        // stage weights for this p (already tf32): ws[i][c][o], pitch 72
#pragma unroll
        for (int it = 0; it < 6; it++) {
            int e = tid + it * NTH;    // 0..1535 float4s
            int i  = e >> 9;
            int r  = e & 511;
            int c  = r >> 4;
            int o4 = r & 15;
            float4 wv = ((const float4*)g_wt2)[p * 1536 + e];
            *(float4*)&ws[(i * IN_C + c) * WS_PITCH + o4 * 4] = wv;
        }
        __syncthreads();

        // A fragments (unmasked) for this warp's 32 pixels
        uint32_t afr[2][4][4];
        const uint32_t* xu = (const uint32_t*)xs;
#pragma unroll
        for (int mt = 0; mt < 2; mt++) {
            int rr = r0 + mt * 16;
#pragma unroll
            for (int kk = 0; kk < 4; kk++) {
                int col = kk * 8 + cl;
                afr[mt][kk][0] = xu[rr * XS_PITCH + col];
                afr[mt][kk][1] = xu[(rr + 8) * XS_PITCH + col];
                afr[mt][kk][2] = xu[rr * XS_PITCH + col + 4];
                afr[mt][kk][3] = xu[(rr + 8) * XS_PITCH + col + 4];
            }
        }

#pragma unroll
        for (int i = 0; i < 3; i++) {
            float mA[2][2];
            mA[0][0] = msp[i * 128 + r0];
            mA[0][1] = msp[i * 128 + r0 + 8];
            mA[1][0] = msp[i * 128 + r0 + 16];
            mA[1][1] = msp[i * 128 + r0 + 24];
            bool any = (mA[0][0] + mA[0][1] + mA[1][0] + mA[1][1]) != 0.0f;
            if (!__any_sync(0xffffffffu, any)) continue;   // warp-uniform slab skip

            const uint32_t* wu = (const uint32_t*)(ws + i * IN_C * WS_PITCH);
            const int on = ob + (lane >> 2);
#pragma unroll
            for (int kk = 0; kk < 4; kk++) {
                uint32_t bfr[4][2];
                const int ck = kk * 8 + cl;
#pragma unroll
                for (int n8 = 0; n8 < 4; n8++) {
                    bfr[n8][0] = wu[ck * WS_PITCH + on + n8 * 8];
                    bfr[n8][1] = wu[(ck + 4) * WS_PITCH + on + n8 * 8];
                }
#pragma unroll
                for (int mt = 0; mt < 2; mt++) {
                    uint32_t am[4];
                    am[0] = __float_as_uint(__uint_as_float(afr[mt][kk][0]) * mA[mt][0]);
                    am[1] = __float_as_uint(__uint_as_float(afr[mt][kk][1]) * mA[mt][1]);
                    am[2] = __float_as_uint(__uint_as_float(afr[mt][kk][2]) * mA[mt][0]);
                    am[3] = __float_as_uint(__uint_as_float(afr[mt][kk][3]) * mA[mt][1]);
#pragma unroll
                    for (int n8 = 0; n8 < 4; n8++)
                        mma_tf32(acc[mt][n8], am, bfr[n8]);
                }
            }
        }
    }

    // ---- epilogue: acc -> smem transpose -> coalesced float4 stores ----
    __syncthreads();
    float* obuf = sm;   // [o][j], pitch 132
#pragma unroll
    for (int mt = 0; mt < 2; mt++) {
#pragma unroll
        for (int n8 = 0; n8 < 4; n8++) {
            int o = ob + n8 * 8 + cl * 2;
            int j = jb + mt * 16 + (lane >> 2);
            obuf[o * OB_PITCH + j]           = acc[mt][n8][0];
            obuf[(o + 1) * OB_PITCH + j]     = acc[mt][n8][1];
            obuf[o * OB_PITCH + j + 8]       = acc[mt][n8][2];
            obuf[(o + 1) * OB_PITCH + j + 8] = acc[mt][n8][3];
        }
    }
    __syncthreads();
#pragma unroll
    for (int it = 0; it < 8; it++) {
        int e  = tid + it * NTH;   // 0..2047 over (o, j4)
        int o  = e >> 5;
        int j4 = e & 31;
        float4 v = *(const float4*)&obuf[o * OB_PITCH + j4 * 4];
        *(float4*)&out[((size_t)(n * OUT_C + o)) * (HWDIM * HWDIM)
                       + h * HWDIM + wb + j4 * 4] = v;
    }
}

extern "C" void kernel_launch(void* const* d_in, const int* in_sizes, int n_in,
                              void* d_out, int out_size) {
    const float* x    = (const float*)d_in[0];
    const float* disp = (const float*)d_in[1];
    const float* fx   = (const float*)d_in[2];
    const float* bl   = (const float*)d_in[3];
    const float* w0   = (const float*)d_in[4];
    const float* w1   = (const float*)d_in[5];
    const float* w2   = (const float*)d_in[6];
    float* out = (float*)d_out;

    prep_weights<<<(KK * 3 * IN_C * OUT_C + 255) / 256, 256>>>(w0, w1, w2);
    conv25d_mma<<<1024, NTH>>>(x, disp, fx, bl, out);
}

// round 6
// speedup vs baseline: 4.5142x; 1.5162x over previous
#include <cuda_runtime.h>
#include <cuda_fp16.h>
#include <cstdint>

#define KK     9
#define IN_C   32
#define OUT_C  64
#define HWDIM  256
#define NTH    256

// static smem byte layout:
//  xs: half [3][130][pitch 40]  = 31200 B   (x rows, fp16, halo cols)
//  ws: half [3][64][pitch 40]   = 15360 B   (weights for current p)
//  ds: float [3][132]           = 1584 B    (disp rows)
//  pk: half2 [3][4][2][8]       = 768 B     (packed masks (m[r], m[r+8]))
#define OFF_WS 31200
#define OFF_DS (OFF_WS + 15360)     // 46560
#define OFF_PK (OFF_DS + 1584)      // 48144
#define SMEM_BYTES (OFF_PK + 768)   // 48912 <= 49152 (static limit)
#define OB_PITCH 132                // epilogue obuf [64][132] floats overlays smem

// pre-transposed fp16 weights as half2 words: g_wth[((p*3+i)*64+o)*16 + cp]
__device__ uint32_t g_wth[KK * 3 * OUT_C * 16];

__global__ void prep_weights(const float* __restrict__ w0,
                             const float* __restrict__ w1,
                             const float* __restrict__ w2) {
    int idx = blockIdx.x * blockDim.x + threadIdx.x;
    if (idx >= KK * 3 * OUT_C * 16) return;
    int p  = idx / 3072;
    int r  = idx % 3072;
    int i  = r >> 10;
    int o  = (r >> 4) & 63;
    int cp = r & 15;
    const float* w = (i == 0) ? w0 : (i == 1) ? w1 : w2;
    float v0 = w[(o * IN_C + 2 * cp) * KK + p];
    float v1 = w[(o * IN_C + 2 * cp + 1) * KK + p];
    __half2 h = __halves2half2(__float2half(v0), __float2half(v1));
    g_wth[idx] = *(uint32_t*)&h;
}

__device__ __forceinline__ void mma_f16(float* d, const uint32_t* a, const uint32_t* b) {
    asm volatile(
        "mma.sync.aligned.m16n8k16.row.col.f32.f16.f16.f32 "
        "{%0,%1,%2,%3}, {%4,%5,%6,%7}, {%8,%9}, {%0,%1,%2,%3};"
        : "+f"(d[0]), "+f"(d[1]), "+f"(d[2]), "+f"(d[3])
        : "r"(a[0]), "r"(a[1]), "r"(a[2]), "r"(a[3]), "r"(b[0]), "r"(b[1]));
}

__device__ __forceinline__ uint32_t hmul2u(uint32_t a, uint32_t m) {
    __half2 r = __hmul2(*(__half2*)&a, *(__half2*)&m);
    return *(uint32_t*)&r;
}

__global__ void __launch_bounds__(NTH)
conv25d_h2(const float* __restrict__ x,
           const float* __restrict__ disp,
           const float* __restrict__ fxp,
           const float* __restrict__ blp,
           float* __restrict__ out) {
    __shared__ __align__(16) char smem[SMEM_BYTES];
    float*  ds = (float*)(smem + OFF_DS);
    __half* pkh = (__half*)(smem + OFF_PK);

    const int tid  = threadIdx.x;
    const int lane = tid & 31;
    const int wrp  = tid >> 5;
    const int g    = lane >> 2;
    const int cl   = lane & 3;
    const int jb   = (wrp & 3) << 5;    // pixel-tile base
    const int ob   = (wrp >> 2) << 5;   // out-channel half

    const int b   = blockIdx.x;         // 1024 CTAs
    const int n   = b >> 9;
    const int rem = b & 511;
    const int h   = rem >> 1;
    const int wb  = (rem & 1) << 7;

    const float* xb = x + (size_t)n * IN_C * (HWDIM * HWDIM);
    const float* db = disp + (size_t)n * (HWDIM * HWDIM);

    // ---- stage disp rows: ds[di][j], gx = wb-1+j, OOB -> 0 ----
    for (int e = tid; e < 3 * 130; e += NTH) {
        int di = e / 130, j = e % 130;
        int gy = h + di - 1, gx = wb - 1 + j;
        float v = 0.0f;
        if (gy >= 0 && gy < HWDIM && gx >= 0 && gx < HWDIM) v = db[gy * HWDIM + gx];
        ds[di * 132 + j] = v;
    }

    // ---- stage x rows (fp16): plane = (di, cpair), row pitch 80 B ----
    for (int pl = wrp; pl < 48; pl += 8) {
        int di = pl >> 4, cp = pl & 15;
        int gy = h + di - 1;
        bool rowok = (gy >= 0) && (gy < HWDIM);
        const float* x0 = xb + (2 * cp) * (HWDIM * HWDIM) + gy * HWDIM;
        const float* x1 = x0 + (HWDIM * HWDIM);
        for (int j = lane; j < 130; j += 32) {
            int gx = wb - 1 + j;
            float v0 = 0.0f, v1 = 0.0f;
            if (rowok && gx >= 0 && gx < HWDIM) { v0 = x0[gx]; v1 = x1[gx]; }
            __half2 hh = __halves2half2(__float2half(v0), __float2half(v1));
            *(uint32_t*)(smem + (di * 130 + j) * 80 + cp * 4) = *(uint32_t*)&hh;
        }
    }

    // ---- per-pixel center quantities (thread=pixel, exact fp32) ----
    float bf = 0.f, depthC = 0.f, grv = 0.f, halfv = 0.f;
    bool validC = false;
    if (tid < 128) {
        const float fxv = fxp[n];
        bf = __fmul_rn(blp[n], fxv);
        float dC = db[h * HWDIM + wb + tid];
        validC = (dC != 0.0f);
        depthC = __fdiv_rn(bf, fminf(fmaxf(validC ? dC : 0.0f, 0.01f), 256.0f));
        grv    = __fdiv_rn(__fmul_rn(16.0f, depthC), fxv);
        halfv  = __fmul_rn(grv, 0.5f);
    }

    float acc[2][4][4];
#pragma unroll
    for (int mt = 0; mt < 2; mt++)
#pragma unroll
        for (int n8 = 0; n8 < 4; n8++)
#pragma unroll
            for (int q = 0; q < 4; q++) acc[mt][n8][q] = 0.0f;

    // pk write indices for this thread's pixel
    const int mw  = tid >> 5;
    const int mmt = (tid >> 4) & 1;
    const int mh  = (tid >> 3) & 1;
    const int mg  = tid & 7;

    for (int p = 0; p < KK; p++) {
        __syncthreads();                 // previous p's ws/pk reads done
        const int di = p / 3, dj = p % 3;

        // masks for this p (bit-exact fp32), packed as (m[r], m[r+8]) half pairs
        if (tid < 128) {
            float dp = ds[di * 132 + dj + tid];
            const bool valid = (dp != 0.0f) && validC;
            const float depth = __fdiv_rn(bf, fminf(fmaxf(valid ? dp : 0.0f, 0.01f), 256.0f));
            const float m0 = (fabsf(__fsub_rn(depth, __fadd_rn(depthC, grv))) <= halfv) ? 1.0f : 0.0f;
            const float ind = (fabsf(__fsub_rn(depth, depthC)) <= halfv) ? 1.0f : 0.0f;
            const float m1 = valid ? ind : 1.0f;
            const float m2 = (fabsf(__fsub_rn(depth, __fsub_rn(depthC, grv))) <= halfv) ? 1.0f : 0.0f;
            int base = ((mw * 2 + mmt) * 8 + mg) * 2 + mh;
            pkh[base]       = __float2half(m0);
            pkh[128 + base] = __float2half(m1);
            pkh[256 + base] = __float2half(m2);
        }

        // stage weights for this p: ws[i][o][cpair] half2, conflict-free
        {
            const uint32_t* src = g_wth + p * 3072;
#pragma unroll
            for (int it = 0; it < 12; it++) {
                int e = tid + it * NTH;       // 0..3071
                int i = e >> 10;
                int o = (e >> 4) & 63;
                int cp = e & 15;
                *(uint32_t*)(smem + OFF_WS + (i * 64 + o) * 80 + cp * 4) = src[e];
            }
        }
        __syncthreads();

        // A fragments (unmasked fp16) for this warp's 32 pixels
        uint32_t afr[2][2][4];
        {
            const char* xp = smem + (di * 130 + dj) * 80;
#pragma unroll
            for (int mt = 0; mt < 2; mt++) {
                int r0 = (jb + mt * 16 + g) * 80;
#pragma unroll
                for (int ks = 0; ks < 2; ks++) {
                    int cb = (cl * 2 + ks * 16) * 2;
                    afr[mt][ks][0] = *(const uint32_t*)(xp + r0 + cb);
                    afr[mt][ks][1] = *(const uint32_t*)(xp + r0 + 640 + cb);
                    afr[mt][ks][2] = *(const uint32_t*)(xp + r0 + cb + 16);
                    afr[mt][ks][3] = *(const uint32_t*)(xp + r0 + 640 + cb + 16);
                }
            }
        }

        const uint32_t* pku = (const uint32_t*)(smem + OFF_PK);
#pragma unroll
        for (int i = 0; i < 3; i++) {
            uint32_t pk0 = pku[(i * 4 + (jb >> 5)) * 16 + g];
            uint32_t pk1 = pku[(i * 4 + (jb >> 5)) * 16 + 8 + g];
            if (!__any_sync(0xffffffffu, (pk0 | pk1) != 0u)) continue;

            __half2 p0 = *(__half2*)&pk0, p1 = *(__half2*)&pk1;
            __half2 lo0 = __half2half2(__low2half(p0)), hi0 = __half2half2(__high2half(p0));
            __half2 lo1 = __half2half2(__low2half(p1)), hi1 = __half2half2(__high2half(p1));
            uint32_t ml[2], mh2[2];
            ml[0] = *(uint32_t*)&lo0; mh2[0] = *(uint32_t*)&hi0;
            ml[1] = *(uint32_t*)&lo1; mh2[1] = *(uint32_t*)&hi1;

            const char* wp = smem + OFF_WS + i * 64 * 80;
#pragma unroll
            for (int ks = 0; ks < 2; ks++) {
                uint32_t bfr[4][2];
                const int kb = (ks * 16 + cl * 2) * 2;
#pragma unroll
                for (int n8 = 0; n8 < 4; n8++) {
                    int o = ob + n8 * 8 + g;
                    bfr[n8][0] = *(const uint32_t*)(wp + o * 80 + kb);
                    bfr[n8][1] = *(const uint32_t*)(wp + o * 80 + kb + 16);
                }
#pragma unroll
                for (int mt = 0; mt < 2; mt++) {
                    uint32_t am[4];
                    am[0] = hmul2u(afr[mt][ks][0], ml[mt]);
                    am[1] = hmul2u(afr[mt][ks][1], mh2[mt]);
                    am[2] = hmul2u(afr[mt][ks][2], ml[mt]);
                    am[3] = hmul2u(afr[mt][ks][3], mh2[mt]);
#pragma unroll
                    for (int n8 = 0; n8 < 4; n8++)
                        mma_f16(acc[mt][n8], am, bfr[n8]);
                }
            }
        }
    }

    // ---- epilogue: acc -> smem transpose -> coalesced float4 stores ----
    __syncthreads();
    float* obuf = (float*)smem;   // [o][j], pitch 132
#pragma unroll
    for (int mt = 0; mt < 2; mt++) {
#pragma unroll
        for (int n8 = 0; n8 < 4; n8++) {
            int o = ob + n8 * 8 + cl * 2;
            int j = jb + mt * 16 + g;
            obuf[o * OB_PITCH + j]           = acc[mt][n8][0];
            obuf[(o + 1) * OB_PITCH + j]     = acc[mt][n8][1];
            obuf[o * OB_PITCH + j + 8]       = acc[mt][n8][2];
            obuf[(o + 1) * OB_PITCH + j + 8] = acc[mt][n8][3];
        }
    }
    __syncthreads();
#pragma unroll
    for (int it = 0; it < 8; it++) {
        int e  = tid + it * NTH;   // (o, j4)
        int o  = e >> 5;
        int j4 = e & 31;
        float4 v = *(const float4*)&obuf[o * OB_PITCH + j4 * 4];
        *(float4*)&out[((size_t)(n * OUT_C + o)) * (HWDIM * HWDIM)
                       + h * HWDIM + wb + j4 * 4] = v;
    }
}

extern "C" void kernel_launch(void* const* d_in, const int* in_sizes, int n_in,
                              void* d_out, int out_size) {
    const float* x    = (const float*)d_in[0];
    const float* disp = (const float*)d_in[1];
    const float* fx   = (const float*)d_in[2];
    const float* bl   = (const float*)d_in[3];
    const float* w0   = (const float*)d_in[4];
    const float* w1   = (const float*)d_in[5];
    const float* w2   = (const float*)d_in[6];
    float* out = (float*)d_out;

    prep_weights<<<(KK * 3 * OUT_C * 16 + 255) / 256, 256>>>(w0, w1, w2);
    conv25d_h2<<<1024, NTH>>>(x, disp, fx, bl, out);
}